// round 6
// baseline (speedup 1.0000x reference)
#include <cuda_runtime.h>
#include <math.h>

#define BATCH 2048
typedef unsigned long long ull;

// ---------------------------------------------------------------------------
// f32x2 packed helpers (sm_100+)
// ---------------------------------------------------------------------------
__device__ __forceinline__ ull pk2(float a, float b) {
    ull r;
    asm("mov.b64 %0, {%1, %2};" : "=l"(r) : "f"(a), "f"(b));
    return r;
}
__device__ __forceinline__ void upk2(ull v, float& a, float& b) {
    asm("mov.b64 {%0, %1}, %2;" : "=f"(a), "=f"(b) : "l"(v));
}
__device__ __forceinline__ ull fma2(ull a, ull b, ull c) {
    ull d;
    asm("fma.rn.f32x2 %0, %1, %2, %3;" : "=l"(d) : "l"(a), "l"(b), "l"(c));
    return d;
}

// ---------------------------------------------------------------------------
// Packed weight bank (single struct -> ONE symbol copy)
// ---------------------------------------------------------------------------
struct CW {
    ull w1[216];     // conv1  [ci<3 ][k<9][p<8]  pairs (co=2p,2p+1)
    ull w2[576];     // conv2  [ci<16][k<9][p<4]
    ull wy[576];     // dconv1 [ci<8 ][k<9][p<8]
    ull wdp[144];    // dconv2 [ci<16][k<9]  pair (co0,co1)
    float wds[144];  // dconv2 [ci<16][k<9]  co2
};
__device__ CW g_pk;
__constant__ CW c_w;

// Scratch
__device__ float g_part[BATCH * 16];
__device__ float g_q[BATCH * 4];
__device__ float g_Y[5 * 16 * 1024];
__device__ float2 g_V[256];

// ---------------------------------------------------------------------------
// Setup: repack weights; block 7 builds the fixed 16x16 entangling unitary.
// ---------------------------------------------------------------------------
__device__ __forceinline__ float2 cmul(float2 a, float2 b) {
    return make_float2(a.x * b.x - a.y * b.y, a.x * b.y + a.y * b.x);
}

__global__ __launch_bounds__(256) void setup_kernel(
    const float* __restrict__ c1w, const float* __restrict__ c2w,
    const float* __restrict__ d1w, const float* __restrict__ d2w,
    const float* __restrict__ qw, float2* __restrict__ V)
{
    if (blockIdx.x == 7) {
        const int tid = threadIdx.x;
        if (tid >= 16) return;
        float2 st[16];
#pragma unroll
        for (int i = 0; i < 16; i++) st[i] = make_float2(0.f, 0.f);
        st[tid].x = 1.f;
#pragma unroll
        for (int l = 0; l < 3; l++) {
#pragma unroll
            for (int w = 0; w < 4; w++) {
                float phi = qw[(l * 4 + w) * 3 + 0];
                float th  = qw[(l * 4 + w) * 3 + 1];
                float om  = qw[(l * 4 + w) * 3 + 2];
                float ct = cosf(th * 0.5f), stt = sinf(th * 0.5f);
                float a = (phi + om) * 0.5f, d = (phi - om) * 0.5f;
                float ca = cosf(a), sa = sinf(a), cd = cosf(d), sd = sinf(d);
                float2 U00 = make_float2(ct * ca, -ct * sa);
                float2 U01 = make_float2(-stt * cd, -stt * sd);
                float2 U10 = make_float2(stt * cd, -stt * sd);
                float2 U11 = make_float2(ct * ca, ct * sa);
                const int bit = 1 << (3 - w);
#pragma unroll
                for (int i = 0; i < 16; i++) {
                    if (i & bit) continue;
                    float2 a0 = st[i], a1 = st[i | bit];
                    float2 n0 = cmul(U00, a0), n1 = cmul(U10, a0);
                    float2 m0 = cmul(U01, a1), m1 = cmul(U11, a1);
                    st[i]       = make_float2(n0.x + m0.x, n0.y + m0.y);
                    st[i | bit] = make_float2(n1.x + m1.x, n1.y + m1.y);
                }
            }
            const int r = (l % 3) + 1;
#pragma unroll
            for (int w = 0; w < 4; w++) {
                const int cb = 1 << (3 - w);
                const int tb = 1 << (3 - ((w + r) & 3));
#pragma unroll
                for (int i = 0; i < 16; i++) {
                    if ((i & cb) && !(i & tb)) {
                        float2 tmp = st[i]; st[i] = st[i | tb]; st[i | tb] = tmp;
                    }
                }
            }
        }
#pragma unroll
        for (int i = 0; i < 16; i++) V[i * 16 + tid] = st[i];
        return;
    }

    int i = blockIdx.x * 256 + threadIdx.x;
    float* w1f  = (float*)g_pk.w1;
    float* w2f  = (float*)g_pk.w2;
    float* wyf  = (float*)g_pk.wy;
    float* wdpf = (float*)g_pk.wdp;
    if (i < 216) {
        int p = i & 7, t = i >> 3;
        int k = t % 9, ci = t / 9;
        w1f[2 * i]     = c1w[(2 * p) * 27 + ci * 9 + k];
        w1f[2 * i + 1] = c1w[(2 * p + 1) * 27 + ci * 9 + k];
    } else if (i < 792) {
        int j = i - 216;
        int p = j & 3, t = j >> 2;
        int k = t % 9, ci = t / 9;
        w2f[2 * j]     = c2w[(2 * p) * 144 + ci * 9 + k];
        w2f[2 * j + 1] = c2w[(2 * p + 1) * 144 + ci * 9 + k];
    } else if (i < 1368) {
        int j = i - 792;
        int p = j & 7, t = j >> 3;
        int k = t % 9, ci = t / 9;
        wyf[2 * j]     = d1w[(2 * p) * 72 + ci * 9 + k];
        wyf[2 * j + 1] = d1w[(2 * p + 1) * 72 + ci * 9 + k];
    } else if (i < 1512) {
        int j = i - 1368;
        int k = j % 9, ci = j / 9;
        wdpf[2 * j]     = d2w[ci * 9 + k];
        wdpf[2 * j + 1] = d2w[144 + ci * 9 + k];
    } else if (i < 1656) {
        int j = i - 1512;
        int k = j % 9, ci = j / 9;
        g_pk.wds[j] = d2w[288 + ci * 9 + k];
    }
}

// ---------------------------------------------------------------------------
// Fused conv1+conv2+fc, register-blocked.
// Block = 256 threads, one image x 8 output rows.
//   conv1: 160 threads, each 2 h1-rows x 1 col x 16 ch (8 pairs)
//   conv2: 64 threads,  each 4 rows  x 1 col x 8 ch  (4 pairs) + fc partials
// ---------------------------------------------------------------------------
__global__ __launch_bounds__(256) void conv12_kernel(
    const float* __restrict__ in, const float* __restrict__ b1,
    const float* __restrict__ b2, const float* __restrict__ fcw,
    float* __restrict__ part)
{
    __shared__ float s_x[3 * 12 * 34];     // rows y0-2..y0+9, cols -1..32
    __shared__ float s_h1[16 * 10 * 34];   // h1 rows y0-1..y0+8, col halo
    __shared__ float s_b1[16];
    __shared__ float s_b2[8];
    __shared__ float swp[2][4];

    const int b  = blockIdx.y;
    const int ck = blockIdx.x;
    const int y0 = ck * 8;
    const int tid = threadIdx.x;

    if (tid < 16) s_b1[tid] = b1[tid];
    else if (tid < 24) s_b2[tid - 16] = b2[tid - 16];

    const float* inb = in + (size_t)b * 3 * 1024;
    for (int i = tid; i < 3 * 408; i += 256) {
        int c = i / 408, rem = i - c * 408;
        int r = rem / 34, xc = rem - r * 34;
        int gy = y0 - 2 + r, gx = xc - 1;
        float v = 0.f;
        if ((unsigned)gy < 32u && (unsigned)gx < 32u) v = inb[c * 1024 + gy * 32 + gx];
        s_x[i] = v;
    }
    __syncthreads();

    // ---- conv1 phase: 160 threads, P=2 rows ----
    if (tid < 160) {
        const int g = tid >> 5, col = tid & 31;
        const int hr0 = 2 * g;
        if (col < 2) {
            int xc = col ? 33 : 0;
#pragma unroll
            for (int c = 0; c < 16; c++) {
                s_h1[c * 340 + hr0 * 34 + xc] = 0.f;
                s_h1[c * 340 + (hr0 + 1) * 34 + xc] = 0.f;
            }
        }
        ull acc[2][8];
#pragma unroll
        for (int r = 0; r < 2; r++)
#pragma unroll
            for (int p = 0; p < 8; p++)
                acc[r][p] = pk2(s_b1[2 * p], s_b1[2 * p + 1]);

#pragma unroll
        for (int ci = 0; ci < 3; ci++) {
            float v[4][3];
#pragma unroll
            for (int rr = 0; rr < 4; rr++)
#pragma unroll
                for (int dx = 0; dx < 3; dx++)
                    v[rr][dx] = s_x[ci * 408 + (hr0 + rr) * 34 + col + dx];
#pragma unroll
            for (int rr = 0; rr < 4; rr++)
#pragma unroll
                for (int dx = 0; dx < 3; dx++) {
                    ull vv = pk2(v[rr][dx], v[rr][dx]);
#pragma unroll
                    for (int r = 0; r < 2; r++) {
                        int dy = rr - r;
                        if (dy < 0 || dy > 2) continue;
                        int k = dy * 3 + dx;
#pragma unroll
                        for (int p = 0; p < 8; p++)
                            acc[r][p] = fma2(vv, c_w.w1[(ci * 9 + k) * 8 + p], acc[r][p]);
                    }
                }
        }
#pragma unroll
        for (int r = 0; r < 2; r++) {
            const int hr = hr0 + r;
            const int gy = y0 - 1 + hr;
            if ((unsigned)gy < 32u) {
#pragma unroll
                for (int p = 0; p < 8; p++) {
                    float lo, hi;
                    upk2(acc[r][p], lo, hi);
                    s_h1[(2 * p) * 340 + hr * 34 + col + 1]     = fmaxf(lo, 0.f);
                    s_h1[(2 * p + 1) * 340 + hr * 34 + col + 1] = fmaxf(hi, 0.f);
                }
            } else {
#pragma unroll
                for (int c = 0; c < 16; c++)
                    s_h1[c * 340 + hr * 34 + col + 1] = 0.f;
            }
        }
    }
    __syncthreads();

    // ---- conv2 phase: 64 threads, P=4 rows, + fc partials ----
    if (tid < 64) {
        const int g = tid >> 5, col = tid & 31;
        const int ty0 = 4 * g;
        ull acc[4][4];
#pragma unroll
        for (int r = 0; r < 4; r++)
#pragma unroll
            for (int p = 0; p < 4; p++)
                acc[r][p] = pk2(s_b2[2 * p], s_b2[2 * p + 1]);

#pragma unroll
        for (int ci = 0; ci < 16; ci++) {
            float v[6][3];
#pragma unroll
            for (int rr = 0; rr < 6; rr++)
#pragma unroll
                for (int dx = 0; dx < 3; dx++)
                    v[rr][dx] = s_h1[ci * 340 + (ty0 + rr) * 34 + col + dx];
#pragma unroll
            for (int rr = 0; rr < 6; rr++)
#pragma unroll
                for (int dx = 0; dx < 3; dx++) {
                    ull vv = pk2(v[rr][dx], v[rr][dx]);
#pragma unroll
                    for (int r = 0; r < 4; r++) {
                        int dy = rr - r;
                        if (dy < 0 || dy > 2) continue;
                        int k = dy * 3 + dx;
#pragma unroll
                        for (int p = 0; p < 4; p++)
                            acc[r][p] = fma2(vv, c_w.w2[(ci * 9 + k) * 4 + p], acc[r][p]);
                    }
                }
        }
        float h[4][8];
#pragma unroll
        for (int r = 0; r < 4; r++)
#pragma unroll
            for (int p = 0; p < 4; p++) {
                float lo, hi;
                upk2(acc[r][p], lo, hi);
                h[r][2 * p]     = fmaxf(lo, 0.f);
                h[r][2 * p + 1] = fmaxf(hi, 0.f);
            }
        // fc partial dot:  k = c*1024 + y*32 + x
        float pr[4] = {0.f, 0.f, 0.f, 0.f};
#pragma unroll
        for (int c = 0; c < 8; c++)
#pragma unroll
            for (int r = 0; r < 4; r++) {
                int k = c * 1024 + (y0 + ty0 + r) * 32 + col;
#pragma unroll
                for (int j = 0; j < 4; j++)
                    pr[j] = fmaf(h[r][c], __ldg(fcw + j * 8192 + k), pr[j]);
            }
#pragma unroll
        for (int off = 16; off > 0; off >>= 1)
#pragma unroll
            for (int j = 0; j < 4; j++)
                pr[j] += __shfl_down_sync(0xffffffffu, pr[j], off);
        if ((tid & 31) == 0)
#pragma unroll
            for (int j = 0; j < 4; j++) swp[tid >> 5][j] = pr[j];
    }
    __syncthreads();
    if (tid < 4)
        part[b * 16 + ck * 4 + tid] = swp[0][tid] + swp[1][tid];
}

// ---------------------------------------------------------------------------
// Y build (unchanged): one thread per (img, pixel, channel-pair).
// ---------------------------------------------------------------------------
__global__ __launch_bounds__(256) void ybuild_kernel(
    const float* __restrict__ f2w, const float* __restrict__ f2b,
    const float* __restrict__ d1b, float* __restrict__ Y)
{
    const int idx  = blockIdx.x * 256 + threadIdx.x;
    const int px   = idx & 1023;
    const int pair = (idx >> 10) & 7;
    const int img  = idx >> 13;
    const int y = px >> 5, x = px & 31;

    ull acc = (img == 4) ? pk2(d1b[2 * pair], d1b[2 * pair + 1]) : pk2(0.f, 0.f);
#pragma unroll
    for (int ci = 0; ci < 8; ci++) {
#pragma unroll
        for (int dy = 0; dy < 3; dy++) {
            int gy = y + dy - 1;
            if ((unsigned)gy >= 32u) continue;
#pragma unroll
            for (int dx = 0; dx < 3; dx++) {
                int gx = x + dx - 1;
                if ((unsigned)gx >= 32u) continue;
                int k = ci * 1024 + gy * 32 + gx;
                float v = (img < 4) ? __ldg(f2w + (size_t)k * 4 + img) : __ldg(f2b + k);
                acc = fma2(pk2(v, v), c_w.wy[(ci * 9 + dy * 3 + dx) * 8 + pair], acc);
            }
        }
    }
    float lo, hi;
    upk2(acc, lo, hi);
    Y[img * 16384 + (2 * pair) * 1024 + px]     = lo;
    Y[img * 16384 + (2 * pair + 1) * 1024 + px] = hi;
}

// ---------------------------------------------------------------------------
// Quantum batched (unchanged)
// ---------------------------------------------------------------------------
__global__ __launch_bounds__(128) void quantum_kernel(
    const float* __restrict__ part, const float* __restrict__ fcb,
    const float2* __restrict__ V, float* __restrict__ qout)
{
    __shared__ float2 sV[256];
    for (int i = threadIdx.x; i < 256; i += 128) sV[i] = V[i];
    __syncthreads();

    const int b = blockIdx.x * 128 + threadIdx.x;

    float c[4], s[4];
#pragma unroll
    for (int w = 0; w < 4; w++) {
        float ang = part[b * 16 + 0 + w] + part[b * 16 + 4 + w]
                  + part[b * 16 + 8 + w] + part[b * 16 + 12 + w] + fcb[w];
        float half = ang * 0.5f;
        c[w] = cosf(half);
        s[w] = sinf(half);
    }

    float2 amp[16];
#pragma unroll
    for (int i = 0; i < 16; i++) {
        float m = ((i >> 3) & 1 ? s[0] : c[0]) * ((i >> 2) & 1 ? s[1] : c[1])
                * ((i >> 1) & 1 ? s[2] : c[2]) * ((i) & 1 ? s[3] : c[3]);
        int pc = __popc(i) & 3;
        amp[i] = (pc == 0) ? make_float2(m, 0.f)
               : (pc == 1) ? make_float2(0.f, -m)
               : (pc == 2) ? make_float2(-m, 0.f)
                           : make_float2(0.f, m);
    }

    float2 t[16];
#pragma unroll
    for (int i = 0; i < 16; i++) t[i] = make_float2(0.f, 0.f);
#pragma unroll
    for (int k = 0; k < 16; k++) {
        float2 a = amp[k];
#pragma unroll
        for (int i = 0; i < 16; i++) {
            float2 v = sV[i * 16 + k];
            t[i].x = fmaf(v.x, a.x, fmaf(-v.y, a.y, t[i].x));
            t[i].y = fmaf(v.x, a.y, fmaf(v.y, a.x, t[i].y));
        }
    }

    float p[16];
#pragma unroll
    for (int i = 0; i < 16; i++) p[i] = t[i].x * t[i].x + t[i].y * t[i].y;
#pragma unroll
    for (int w = 0; w < 4; w++) {
        const int bit = 1 << (3 - w);
        float ev = 0.f;
#pragma unroll
        for (int i = 0; i < 16; i++) ev += (i & bit) ? -p[i] : p[i];
        qout[b * 4 + w] = ev;
    }
}

// ---------------------------------------------------------------------------
// Fused output, batch-grouped: Y tile in smem once; 4 passes x 4 batches;
// each batch served by 128 threads (combine f32x2 pairs; conv P=2 rows).
// ---------------------------------------------------------------------------
#define YT 5440            // 16 * 340
__global__ __launch_bounds__(512) void fused_out_kernel(
    const float* __restrict__ q, const float* __restrict__ Y,
    const float* __restrict__ bias, float* __restrict__ out)
{
    extern __shared__ float smem[];
    float* sY = smem;               // 5 * YT
    float* sH = smem + 5 * YT;      // 4 * YT

    const int ck = blockIdx.x;
    const int y0 = ck * 8;
    const int b0 = blockIdx.y * 16;
    const int tid = threadIdx.x;

    __shared__ float s_b[3];
    if (tid < 3) s_b[tid] = bias[tid];

    // Load Y tile: thread owns (r, xc); loops 80 planes.
    if (tid < 340) {
        const int r = tid / 34, xc = tid - 34 * r;
        const int gy = y0 + r - 1, gx = xc - 1;
        const bool ok = ((unsigned)gy < 32u) && ((unsigned)gx < 32u);
        const int goff = gy * 32 + gx;
#pragma unroll 4
        for (int pl = 0; pl < 80; pl++)
            sY[pl * 340 + tid] = ok ? __ldg(Y + pl * 1024 + goff) : 0.f;
    }
    __syncthreads();

    const int qg = tid >> 7;          // batch slot 0..3
    const int ltid = tid & 127;
    const int col = ltid & 31, rg = ltid >> 5;
    const int ty0 = 2 * rg;
    float* sHq = sH + qg * YT;
    const float2* sY2 = (const float2*)sY;
    float2* sH2 = (float2*)sHq;

    for (int pass = 0; pass < 4; pass++) {
        const int b = b0 + pass * 4 + qg;
        const float q0 = __ldg(q + b * 4 + 0), q1 = __ldg(q + b * 4 + 1);
        const float q2 = __ldg(q + b * 4 + 2), q3 = __ldg(q + b * 4 + 3);

        // combine + relu (float2 pairs)
        for (int i = ltid; i < 2720; i += 128) {
            float2 a0 = sY2[i],          a1 = sY2[2720 + i];
            float2 a2 = sY2[5440 + i],   a3 = sY2[8160 + i];
            float2 a4 = sY2[10880 + i];
            float vx = fmaf(q0, a0.x, fmaf(q1, a1.x, fmaf(q2, a2.x, fmaf(q3, a3.x, a4.x))));
            float vy = fmaf(q0, a0.y, fmaf(q1, a1.y, fmaf(q2, a2.y, fmaf(q3, a3.y, a4.y))));
            sH2[i] = make_float2(fmaxf(vx, 0.f), fmaxf(vy, 0.f));
        }
        __syncthreads();

        // dconv2: P=2 rows per thread
        ull acc2[2];
        float accs[2];
        acc2[0] = acc2[1] = pk2(s_b[0], s_b[1]);
        accs[0] = accs[1] = s_b[2];
#pragma unroll
        for (int ci = 0; ci < 16; ci++) {
            float v[4][3];
#pragma unroll
            for (int rr = 0; rr < 4; rr++)
#pragma unroll
                for (int dx = 0; dx < 3; dx++)
                    v[rr][dx] = sHq[ci * 340 + (ty0 + rr) * 34 + col + dx];
#pragma unroll
            for (int rr = 0; rr < 4; rr++)
#pragma unroll
                for (int dx = 0; dx < 3; dx++) {
                    ull vv = pk2(v[rr][dx], v[rr][dx]);
#pragma unroll
                    for (int r = 0; r < 2; r++) {
                        int dy = rr - r;
                        if (dy < 0 || dy > 2) continue;
                        int k = dy * 3 + dx;
                        acc2[r] = fma2(vv, c_w.wdp[ci * 9 + k], acc2[r]);
                        accs[r] = fmaf(v[rr][dx], c_w.wds[ci * 9 + k], accs[r]);
                    }
                }
        }
#pragma unroll
        for (int r = 0; r < 2; r++) {
            float lo, hi;
            upk2(acc2[r], lo, hi);
            float* outp = out + (size_t)b * 3 * 1024 + (y0 + ty0 + r) * 32 + col;
            outp[0]    = __fdividef(1.f, 1.f + __expf(-lo));
            outp[1024] = __fdividef(1.f, 1.f + __expf(-hi));
            outp[2048] = __fdividef(1.f, 1.f + __expf(-accs[r]));
        }
        __syncthreads();
    }
}

// ---------------------------------------------------------------------------

extern "C" void kernel_launch(void* const* d_in, const int* in_sizes, int n_in,
                              void* d_out, int out_size)
{
    const float* x   = (const float*)d_in[0];
    const float* c1w = (const float*)d_in[1];
    const float* c1b = (const float*)d_in[2];
    const float* c2w = (const float*)d_in[3];
    const float* c2b = (const float*)d_in[4];
    const float* fcw = (const float*)d_in[5];
    const float* fcb = (const float*)d_in[6];
    const float* qw  = (const float*)d_in[7];
    const float* f2w = (const float*)d_in[8];
    const float* f2b = (const float*)d_in[9];
    const float* d1w = (const float*)d_in[10];
    const float* d1b = (const float*)d_in[11];
    const float* d2w = (const float*)d_in[12];
    const float* d2b = (const float*)d_in[13];
    float* out = (float*)d_out;

    float *part, *qv, *Y, *pk;
    float2* V;
    cudaGetSymbolAddress((void**)&part, g_part);
    cudaGetSymbolAddress((void**)&qv,   g_q);
    cudaGetSymbolAddress((void**)&Y,    g_Y);
    cudaGetSymbolAddress((void**)&V,    g_V);
    cudaGetSymbolAddress((void**)&pk,   g_pk);

    cudaFuncSetAttribute(fused_out_kernel,
                         cudaFuncAttributeMaxDynamicSharedMemorySize,
                         9 * YT * 4);

    setup_kernel<<<8, 256>>>(c1w, c2w, d1w, d2w, qw, V);
    cudaMemcpyToSymbolAsync(c_w, pk, sizeof(CW), 0, cudaMemcpyDeviceToDevice, 0);

    ybuild_kernel<<<160, 256>>>(f2w, f2b, d1b, Y);
    conv12_kernel<<<dim3(4, BATCH), 256>>>(x, c1b, c2b, fcw, part);
    quantum_kernel<<<BATCH / 128, 128>>>(part, fcb, V, qv);
    fused_out_kernel<<<dim3(4, BATCH / 16), 512, 9 * YT * 4>>>(qv, Y, d2b, out);
}

// round 7
// speedup vs baseline: 1.2346x; 1.2346x over previous
#include <cuda_runtime.h>
#include <math.h>

#define BATCH 2048
typedef unsigned long long ull;

// ---------------------------------------------------------------------------
// f32x2 packed helpers (sm_100+)
// ---------------------------------------------------------------------------
__device__ __forceinline__ ull pk2(float a, float b) {
    ull r;
    asm("mov.b64 %0, {%1, %2};" : "=l"(r) : "f"(a), "f"(b));
    return r;
}
__device__ __forceinline__ void upk2(ull v, float& a, float& b) {
    asm("mov.b64 {%0, %1}, %2;" : "=f"(a), "=f"(b) : "l"(v));
}
__device__ __forceinline__ ull fma2(ull a, ull b, ull c) {
    ull d;
    asm("fma.rn.f32x2 %0, %1, %2, %3;" : "=l"(d) : "l"(a), "l"(b), "l"(c));
    return d;
}

// ---------------------------------------------------------------------------
// Packed weight bank (single struct -> ONE symbol copy)
// ---------------------------------------------------------------------------
struct CW {
    ull w1[216];     // conv1  [ci<3 ][k<9][p<8]  pairs (co=2p,2p+1)
    ull w2[576];     // conv2  [ci<16][k<9][p<4]
    ull wy[576];     // dconv1 [ci<8 ][k<9][p<8]
    ull wdp[144];    // dconv2 [ci<16][k<9]  pair (co0,co1)
    float wds[144];  // dconv2 [ci<16][k<9]  co2
};
__device__ CW g_pk;
__constant__ CW c_w;

// Scratch
__device__ float g_part[BATCH * 8];
__device__ float g_q[BATCH * 4];
__device__ float g_Y[5 * 16 * 1024];
__device__ float2 g_V[256];

// ---------------------------------------------------------------------------
// Setup: repack weights; block 7 builds the fixed 16x16 entangling unitary.
// ---------------------------------------------------------------------------
__device__ __forceinline__ float2 cmul(float2 a, float2 b) {
    return make_float2(a.x * b.x - a.y * b.y, a.x * b.y + a.y * b.x);
}

__global__ __launch_bounds__(256) void setup_kernel(
    const float* __restrict__ c1w, const float* __restrict__ c2w,
    const float* __restrict__ d1w, const float* __restrict__ d2w,
    const float* __restrict__ qw, float2* __restrict__ V)
{
    if (blockIdx.x == 7) {
        const int tid = threadIdx.x;
        if (tid >= 16) return;
        float2 st[16];
#pragma unroll
        for (int i = 0; i < 16; i++) st[i] = make_float2(0.f, 0.f);
        st[tid].x = 1.f;
#pragma unroll
        for (int l = 0; l < 3; l++) {
#pragma unroll
            for (int w = 0; w < 4; w++) {
                float phi = qw[(l * 4 + w) * 3 + 0];
                float th  = qw[(l * 4 + w) * 3 + 1];
                float om  = qw[(l * 4 + w) * 3 + 2];
                float ct = cosf(th * 0.5f), stt = sinf(th * 0.5f);
                float a = (phi + om) * 0.5f, d = (phi - om) * 0.5f;
                float ca = cosf(a), sa = sinf(a), cd = cosf(d), sd = sinf(d);
                float2 U00 = make_float2(ct * ca, -ct * sa);
                float2 U01 = make_float2(-stt * cd, -stt * sd);
                float2 U10 = make_float2(stt * cd, -stt * sd);
                float2 U11 = make_float2(ct * ca, ct * sa);
                const int bit = 1 << (3 - w);
#pragma unroll
                for (int i = 0; i < 16; i++) {
                    if (i & bit) continue;
                    float2 a0 = st[i], a1 = st[i | bit];
                    float2 n0 = cmul(U00, a0), n1 = cmul(U10, a0);
                    float2 m0 = cmul(U01, a1), m1 = cmul(U11, a1);
                    st[i]       = make_float2(n0.x + m0.x, n0.y + m0.y);
                    st[i | bit] = make_float2(n1.x + m1.x, n1.y + m1.y);
                }
            }
            const int r = (l % 3) + 1;
#pragma unroll
            for (int w = 0; w < 4; w++) {
                const int cb = 1 << (3 - w);
                const int tb = 1 << (3 - ((w + r) & 3));
#pragma unroll
                for (int i = 0; i < 16; i++) {
                    if ((i & cb) && !(i & tb)) {
                        float2 tmp = st[i]; st[i] = st[i | tb]; st[i | tb] = tmp;
                    }
                }
            }
        }
#pragma unroll
        for (int i = 0; i < 16; i++) V[i * 16 + tid] = st[i];
        return;
    }

    int i = blockIdx.x * 256 + threadIdx.x;
    float* w1f  = (float*)g_pk.w1;
    float* w2f  = (float*)g_pk.w2;
    float* wyf  = (float*)g_pk.wy;
    float* wdpf = (float*)g_pk.wdp;
    if (i < 216) {
        int p = i & 7, t = i >> 3;
        int k = t % 9, ci = t / 9;
        w1f[2 * i]     = c1w[(2 * p) * 27 + ci * 9 + k];
        w1f[2 * i + 1] = c1w[(2 * p + 1) * 27 + ci * 9 + k];
    } else if (i < 792) {
        int j = i - 216;
        int p = j & 3, t = j >> 2;
        int k = t % 9, ci = t / 9;
        w2f[2 * j]     = c2w[(2 * p) * 144 + ci * 9 + k];
        w2f[2 * j + 1] = c2w[(2 * p + 1) * 144 + ci * 9 + k];
    } else if (i < 1368) {
        int j = i - 792;
        int p = j & 7, t = j >> 3;
        int k = t % 9, ci = t / 9;
        wyf[2 * j]     = d1w[(2 * p) * 72 + ci * 9 + k];
        wyf[2 * j + 1] = d1w[(2 * p + 1) * 72 + ci * 9 + k];
    } else if (i < 1512) {
        int j = i - 1368;
        int k = j % 9, ci = j / 9;
        wdpf[2 * j]     = d2w[ci * 9 + k];
        wdpf[2 * j + 1] = d2w[144 + ci * 9 + k];
    } else if (i < 1656) {
        int j = i - 1512;
        int k = j % 9, ci = j / 9;
        g_pk.wds[j] = d2w[288 + ci * 9 + k];
    }
}

// ---------------------------------------------------------------------------
// Fused conv1+conv2+fc: 16-row chunks, 512 threads all active.
//   conv1: 576 items (18 h1-rows x 32 cols), thread does 1-2 items
//   conv2: 512 threads = 16 rows x 32 cols, P=1, + fc partials
// ---------------------------------------------------------------------------
__global__ __launch_bounds__(512) void conv12_kernel(
    const float* __restrict__ in, const float* __restrict__ b1,
    const float* __restrict__ b2, const float* __restrict__ fcw,
    float* __restrict__ part)
{
    __shared__ float s_x[3 * 20 * 34];     // x rows y0-2..y0+17, cols -1..32
    __shared__ float s_h1[16 * 18 * 34];   // h1 rows y0-1..y0+16, col halo
    __shared__ float s_b1[16];
    __shared__ float s_b2[8];
    __shared__ float swp[16][4];

    const int b  = blockIdx.y;
    const int ck = blockIdx.x;
    const int y0 = ck * 16;
    const int tid = threadIdx.x;

    if (tid < 16) s_b1[tid] = b1[tid];
    else if (tid < 24) s_b2[tid - 16] = b2[tid - 16];

    const float* inb = in + (size_t)b * 3 * 1024;
    for (int i = tid; i < 3 * 680; i += 512) {
        int c = i / 680, rem = i - c * 680;
        int r = rem / 34, xc = rem - r * 34;
        int gy = y0 - 2 + r, gx = xc - 1;
        float v = 0.f;
        if ((unsigned)gy < 32u && (unsigned)gx < 32u) v = inb[c * 1024 + gy * 32 + gx];
        s_x[i] = v;
    }
    // zero h1 col halo (18 rows x {0,33})
    if (tid < 36) {
        int hr = tid >> 1, xc = (tid & 1) ? 33 : 0;
#pragma unroll
        for (int c = 0; c < 16; c++) s_h1[c * 612 + hr * 34 + xc] = 0.f;
    }
    __syncthreads();

    // ---- conv1: items = 18 rows x 32 cols ----
    for (int it = tid; it < 576; it += 512) {
        const int hr = it >> 5, col = it & 31;
        const int gy = y0 - 1 + hr;
        if ((unsigned)gy < 32u) {
            ull acc[8];
#pragma unroll
            for (int p = 0; p < 8; p++) acc[p] = pk2(s_b1[2 * p], s_b1[2 * p + 1]);
#pragma unroll
            for (int ci = 0; ci < 3; ci++) {
                float v[9];
#pragma unroll
                for (int dy = 0; dy < 3; dy++)
#pragma unroll
                    for (int dx = 0; dx < 3; dx++)
                        v[dy * 3 + dx] = s_x[ci * 680 + (hr + dy) * 34 + col + dx];
#pragma unroll
                for (int k = 0; k < 9; k++) {
                    ull vv = pk2(v[k], v[k]);
#pragma unroll
                    for (int p = 0; p < 8; p++)
                        acc[p] = fma2(vv, c_w.w1[(ci * 9 + k) * 8 + p], acc[p]);
                }
            }
#pragma unroll
            for (int p = 0; p < 8; p++) {
                float lo, hi;
                upk2(acc[p], lo, hi);
                s_h1[(2 * p) * 612 + hr * 34 + col + 1]     = fmaxf(lo, 0.f);
                s_h1[(2 * p + 1) * 612 + hr * 34 + col + 1] = fmaxf(hi, 0.f);
            }
        } else {
#pragma unroll
            for (int c = 0; c < 16; c++)
                s_h1[c * 612 + hr * 34 + col + 1] = 0.f;
        }
    }
    __syncthreads();

    // ---- conv2: 512 threads = 16 rows x 32 cols + fc partials ----
    {
        const int tx = tid & 31, ty = tid >> 5;
        ull acc2[4];
#pragma unroll
        for (int p = 0; p < 4; p++) acc2[p] = pk2(s_b2[2 * p], s_b2[2 * p + 1]);
#pragma unroll
        for (int ci = 0; ci < 16; ci++) {
            float v[9];
#pragma unroll
            for (int dy = 0; dy < 3; dy++)
#pragma unroll
                for (int dx = 0; dx < 3; dx++)
                    v[dy * 3 + dx] = s_h1[ci * 612 + (ty + dy) * 34 + tx + dx];
#pragma unroll
            for (int k = 0; k < 9; k++) {
                ull vv = pk2(v[k], v[k]);
#pragma unroll
                for (int p = 0; p < 4; p++)
                    acc2[p] = fma2(vv, c_w.w2[(ci * 9 + k) * 4 + p], acc2[p]);
            }
        }
        const int y = y0 + ty;
        float h[8];
#pragma unroll
        for (int p = 0; p < 4; p++) {
            float lo, hi;
            upk2(acc2[p], lo, hi);
            h[2 * p]     = fmaxf(lo, 0.f);
            h[2 * p + 1] = fmaxf(hi, 0.f);
        }
        float pr[4] = {0.f, 0.f, 0.f, 0.f};
#pragma unroll
        for (int c = 0; c < 8; c++) {
            int k = c * 1024 + y * 32 + tx;
#pragma unroll
            for (int j = 0; j < 4; j++)
                pr[j] = fmaf(h[c], __ldg(fcw + j * 8192 + k), pr[j]);
        }
#pragma unroll
        for (int off = 16; off > 0; off >>= 1)
#pragma unroll
            for (int j = 0; j < 4; j++)
                pr[j] += __shfl_down_sync(0xffffffffu, pr[j], off);
        if (tx == 0)
#pragma unroll
            for (int j = 0; j < 4; j++) swp[ty][j] = pr[j];
    }
    __syncthreads();
    if (tid < 4) {
        float s = 0.f;
#pragma unroll
        for (int wq = 0; wq < 16; wq++) s += swp[wq][tid];
        part[b * 8 + ck * 4 + tid] = s;
    }
}

// ---------------------------------------------------------------------------
// Y build: one thread per (img, pixel, channel-pair).
// ---------------------------------------------------------------------------
__global__ __launch_bounds__(256) void ybuild_kernel(
    const float* __restrict__ f2w, const float* __restrict__ f2b,
    const float* __restrict__ d1b, float* __restrict__ Y)
{
    const int idx  = blockIdx.x * 256 + threadIdx.x;
    const int px   = idx & 1023;
    const int pair = (idx >> 10) & 7;
    const int img  = idx >> 13;
    const int y = px >> 5, x = px & 31;

    ull acc = (img == 4) ? pk2(d1b[2 * pair], d1b[2 * pair + 1]) : pk2(0.f, 0.f);
#pragma unroll
    for (int ci = 0; ci < 8; ci++) {
#pragma unroll
        for (int dy = 0; dy < 3; dy++) {
            int gy = y + dy - 1;
            if ((unsigned)gy >= 32u) continue;
#pragma unroll
            for (int dx = 0; dx < 3; dx++) {
                int gx = x + dx - 1;
                if ((unsigned)gx >= 32u) continue;
                int k = ci * 1024 + gy * 32 + gx;
                float v = (img < 4) ? __ldg(f2w + (size_t)k * 4 + img) : __ldg(f2b + k);
                acc = fma2(pk2(v, v), c_w.wy[(ci * 9 + dy * 3 + dx) * 8 + pair], acc);
            }
        }
    }
    float lo, hi;
    upk2(acc, lo, hi);
    Y[img * 16384 + (2 * pair) * 1024 + px]     = lo;
    Y[img * 16384 + (2 * pair + 1) * 1024 + px] = hi;
}

// ---------------------------------------------------------------------------
// Quantum batched: 64-thread blocks for latency spread.
// ---------------------------------------------------------------------------
__global__ __launch_bounds__(64) void quantum_kernel(
    const float* __restrict__ part, const float* __restrict__ fcb,
    const float2* __restrict__ V, float* __restrict__ qout)
{
    __shared__ float2 sV[256];
    for (int i = threadIdx.x; i < 256; i += 64) sV[i] = V[i];
    __syncthreads();

    const int b = blockIdx.x * 64 + threadIdx.x;

    float c[4], s[4];
#pragma unroll
    for (int w = 0; w < 4; w++) {
        float ang = part[b * 8 + w] + part[b * 8 + 4 + w] + fcb[w];
        float half = ang * 0.5f;
        c[w] = cosf(half);
        s[w] = sinf(half);
    }

    float2 amp[16];
#pragma unroll
    for (int i = 0; i < 16; i++) {
        float m = ((i >> 3) & 1 ? s[0] : c[0]) * ((i >> 2) & 1 ? s[1] : c[1])
                * ((i >> 1) & 1 ? s[2] : c[2]) * ((i) & 1 ? s[3] : c[3]);
        int pc = __popc(i) & 3;
        amp[i] = (pc == 0) ? make_float2(m, 0.f)
               : (pc == 1) ? make_float2(0.f, -m)
               : (pc == 2) ? make_float2(-m, 0.f)
                           : make_float2(0.f, m);
    }

    float2 t[16];
#pragma unroll
    for (int i = 0; i < 16; i++) t[i] = make_float2(0.f, 0.f);
#pragma unroll
    for (int k = 0; k < 16; k++) {
        float2 a = amp[k];
#pragma unroll
        for (int i = 0; i < 16; i++) {
            float2 v = sV[i * 16 + k];
            t[i].x = fmaf(v.x, a.x, fmaf(-v.y, a.y, t[i].x));
            t[i].y = fmaf(v.x, a.y, fmaf(v.y, a.x, t[i].y));
        }
    }

    float p[16];
#pragma unroll
    for (int i = 0; i < 16; i++) p[i] = t[i].x * t[i].x + t[i].y * t[i].y;
#pragma unroll
    for (int w = 0; w < 4; w++) {
        const int bit = 1 << (3 - w);
        float ev = 0.f;
#pragma unroll
        for (int i = 0; i < 16; i++) ev += (i & bit) ? -p[i] : p[i];
        qout[b * 4 + w] = ev;
    }
}

// ---------------------------------------------------------------------------
// Fused output, batch-grouped (R5 structure): Y tile in smem once;
// 8 passes x 2 batches x 256 threads. Combine uses fma.rn.f32x2.
// ---------------------------------------------------------------------------
#define YTILE 5440            // 16*340
__global__ __launch_bounds__(512) void fused_out_kernel(
    const float* __restrict__ q, const float* __restrict__ Y,
    const float* __restrict__ bias, float* __restrict__ out)
{
    extern __shared__ float smem[];
    float* sY = smem;               // 5 * 5440
    float* sH = smem + 5 * YTILE;   // 2 * 5440

    const int ck = blockIdx.x;
    const int y0 = ck * 8;
    const int b0 = blockIdx.y * 16;
    const int tid  = threadIdx.x;
    const int half = tid >> 8;
    const int htid = tid & 255;

    __shared__ float s_b[3];
    if (tid < 3) s_b[tid] = bias[tid];

    // Load Y tile: thread owns (r, xc); loops 80 planes.
    if (tid < 340) {
        const int r = tid / 34, xc = tid - 34 * r;
        const int gy = y0 + r - 1, gx = xc - 1;
        const bool ok = ((unsigned)gy < 32u) && ((unsigned)gx < 32u);
        const int goff = gy * 32 + gx;
#pragma unroll 4
        for (int pl = 0; pl < 80; pl++)
            sY[pl * 340 + tid] = ok ? __ldg(Y + pl * 1024 + goff) : 0.f;
    }
    __syncthreads();

    const int tx = htid & 31, ty = htid >> 5;
    float* sHh = sH + half * YTILE;
    const ull* sY2 = (const ull*)sY;
    ull* sH2 = (ull*)sHh;

    for (int g = 0; g < 8; g++) {
        const int b = b0 + 2 * g + half;
        const float q0 = __ldg(q + b * 4 + 0), q1 = __ldg(q + b * 4 + 1);
        const float q2 = __ldg(q + b * 4 + 2), q3 = __ldg(q + b * 4 + 3);
        const ull Q0 = pk2(q0, q0), Q1 = pk2(q1, q1);
        const ull Q2 = pk2(q2, q2), Q3 = pk2(q3, q3);

        // combine + relu (packed f32x2)
        for (int i = htid; i < 2720; i += 256) {
            ull v = fma2(Q0, sY2[i],
                    fma2(Q1, sY2[2720 + i],
                    fma2(Q2, sY2[5440 + i],
                    fma2(Q3, sY2[8160 + i], sY2[10880 + i]))));
            float lo, hi;
            upk2(v, lo, hi);
            sH2[i] = pk2(fmaxf(lo, 0.f), fmaxf(hi, 0.f));
        }
        __syncthreads();

        // dconv2 (16->3) + sigmoid, P=1
        ull acc2 = pk2(s_b[0], s_b[1]);
        float acc = s_b[2];
#pragma unroll
        for (int ci = 0; ci < 16; ci++) {
            float v[9];
#pragma unroll
            for (int dy = 0; dy < 3; dy++)
#pragma unroll
                for (int dx = 0; dx < 3; dx++)
                    v[dy * 3 + dx] = sHh[ci * 340 + (ty + dy) * 34 + tx + dx];
#pragma unroll
            for (int k = 0; k < 9; k++) {
                ull vv = pk2(v[k], v[k]);
                acc2 = fma2(vv, c_w.wdp[ci * 9 + k], acc2);
                acc  = fmaf(v[k], c_w.wds[ci * 9 + k], acc);
            }
        }
        float r0, r1;
        upk2(acc2, r0, r1);
        float* outp = out + (size_t)b * 3 * 1024 + (y0 + ty) * 32 + tx;
        outp[0]    = __fdividef(1.f, 1.f + __expf(-r0));
        outp[1024] = __fdividef(1.f, 1.f + __expf(-r1));
        outp[2048] = __fdividef(1.f, 1.f + __expf(-acc));
        __syncthreads();
    }
}

// ---------------------------------------------------------------------------

extern "C" void kernel_launch(void* const* d_in, const int* in_sizes, int n_in,
                              void* d_out, int out_size)
{
    const float* x   = (const float*)d_in[0];
    const float* c1w = (const float*)d_in[1];
    const float* c1b = (const float*)d_in[2];
    const float* c2w = (const float*)d_in[3];
    const float* c2b = (const float*)d_in[4];
    const float* fcw = (const float*)d_in[5];
    const float* fcb = (const float*)d_in[6];
    const float* qw  = (const float*)d_in[7];
    const float* f2w = (const float*)d_in[8];
    const float* f2b = (const float*)d_in[9];
    const float* d1w = (const float*)d_in[10];
    const float* d1b = (const float*)d_in[11];
    const float* d2w = (const float*)d_in[12];
    const float* d2b = (const float*)d_in[13];
    float* out = (float*)d_out;

    float *part, *qv, *Y, *pk;
    float2* V;
    cudaGetSymbolAddress((void**)&part, g_part);
    cudaGetSymbolAddress((void**)&qv,   g_q);
    cudaGetSymbolAddress((void**)&Y,    g_Y);
    cudaGetSymbolAddress((void**)&V,    g_V);
    cudaGetSymbolAddress((void**)&pk,   g_pk);

    cudaFuncSetAttribute(fused_out_kernel,
                         cudaFuncAttributeMaxDynamicSharedMemorySize,
                         7 * YTILE * 4);

    setup_kernel<<<8, 256>>>(c1w, c2w, d1w, d2w, qw, V);
    cudaMemcpyToSymbolAsync(c_w, pk, sizeof(CW), 0, cudaMemcpyDeviceToDevice, 0);

    ybuild_kernel<<<160, 256>>>(f2w, f2b, d1b, Y);
    conv12_kernel<<<dim3(2, BATCH), 512>>>(x, c1b, c2b, fcw, part);
    quantum_kernel<<<BATCH / 64, 64>>>(part, fcb, V, qv);
    fused_out_kernel<<<dim3(4, BATCH / 16), 512, 7 * YTILE * 4>>>(qv, Y, d2b, out);
}

// round 8
// speedup vs baseline: 1.2392x; 1.0037x over previous
#include <cuda_runtime.h>
#include <math.h>

#define BATCH 2048
typedef unsigned long long ull;

// ---------------------------------------------------------------------------
// f32x2 packed helpers (sm_100+)
// ---------------------------------------------------------------------------
__device__ __forceinline__ ull pk2(float a, float b) {
    ull r;
    asm("mov.b64 %0, {%1, %2};" : "=l"(r) : "f"(a), "f"(b));
    return r;
}
__device__ __forceinline__ void upk2(ull v, float& a, float& b) {
    asm("mov.b64 {%0, %1}, %2;" : "=f"(a), "=f"(b) : "l"(v));
}
__device__ __forceinline__ ull fma2(ull a, ull b, ull c) {
    ull d;
    asm("fma.rn.f32x2 %0, %1, %2, %3;" : "=l"(d) : "l"(a), "l"(b), "l"(c));
    return d;
}

// ---------------------------------------------------------------------------
// Packed weight bank — vector types so weight reads are LDC.128 / LDC.128x4.
// Byte layout of w1/w2/wy identical to the old ull arrays (pairs adjacent).
// ---------------------------------------------------------------------------
struct CW {
    ulonglong2 w1[108];   // conv1  [(ci*9+k)*4 + pp], pp<4 -> co pairs (2pp,2pp+1)
    ulonglong2 w2[288];   // conv2  [(ci*9+k)*2 + pp], pp<2
    ulonglong2 wy[288];   // dconv1 [(ci*9+k)*4 + pp], pp<4
    ulonglong2 wdp[64];   // dconv2 (co0,co1) [ci*4 + kp], k = 2kp, 2kp+1
    ull        wdp8[16];  // dconv2 (co0,co1) [ci], k = 8
    float4     wds[32];   // dconv2 co2 [ci*2 + h], k = 4h..4h+3
    float      wds8[16];  // dconv2 co2 [ci], k = 8
};
__device__ CW g_pk;
__constant__ CW c_w;

// Scratch
__device__ float g_part[BATCH * 8];
__device__ float g_q[BATCH * 4];
__device__ float g_Y[5 * 16 * 1024];
__device__ float2 g_V[256];

// ---------------------------------------------------------------------------
// Setup: repack weights (float-offset view of CW); block 7 builds the fixed
// 16x16 entangling unitary.
// ---------------------------------------------------------------------------
__device__ __forceinline__ float2 cmul(float2 a, float2 b) {
    return make_float2(a.x * b.x - a.y * b.y, a.x * b.y + a.y * b.x);
}

__global__ __launch_bounds__(256) void setup_kernel(
    const float* __restrict__ c1w, const float* __restrict__ c2w,
    const float* __restrict__ d1w, const float* __restrict__ d2w,
    const float* __restrict__ qw, float2* __restrict__ V)
{
    if (blockIdx.x == 7) {
        const int tid = threadIdx.x;
        if (tid >= 16) return;
        float2 st[16];
#pragma unroll
        for (int i = 0; i < 16; i++) st[i] = make_float2(0.f, 0.f);
        st[tid].x = 1.f;
#pragma unroll
        for (int l = 0; l < 3; l++) {
#pragma unroll
            for (int w = 0; w < 4; w++) {
                float phi = qw[(l * 4 + w) * 3 + 0];
                float th  = qw[(l * 4 + w) * 3 + 1];
                float om  = qw[(l * 4 + w) * 3 + 2];
                float ct = cosf(th * 0.5f), stt = sinf(th * 0.5f);
                float a = (phi + om) * 0.5f, d = (phi - om) * 0.5f;
                float ca = cosf(a), sa = sinf(a), cd = cosf(d), sd = sinf(d);
                float2 U00 = make_float2(ct * ca, -ct * sa);
                float2 U01 = make_float2(-stt * cd, -stt * sd);
                float2 U10 = make_float2(stt * cd, -stt * sd);
                float2 U11 = make_float2(ct * ca, ct * sa);
                const int bit = 1 << (3 - w);
#pragma unroll
                for (int i = 0; i < 16; i++) {
                    if (i & bit) continue;
                    float2 a0 = st[i], a1 = st[i | bit];
                    float2 n0 = cmul(U00, a0), n1 = cmul(U10, a0);
                    float2 m0 = cmul(U01, a1), m1 = cmul(U11, a1);
                    st[i]       = make_float2(n0.x + m0.x, n0.y + m0.y);
                    st[i | bit] = make_float2(n1.x + m1.x, n1.y + m1.y);
                }
            }
            const int r = (l % 3) + 1;
#pragma unroll
            for (int w = 0; w < 4; w++) {
                const int cb = 1 << (3 - w);
                const int tb = 1 << (3 - ((w + r) & 3));
#pragma unroll
                for (int i = 0; i < 16; i++) {
                    if ((i & cb) && !(i & tb)) {
                        float2 tmp = st[i]; st[i] = st[i | tb]; st[i | tb] = tmp;
                    }
                }
            }
        }
#pragma unroll
        for (int i = 0; i < 16; i++) V[i * 16 + tid] = st[i];
        return;
    }

    int i = blockIdx.x * 256 + threadIdx.x;
    float* pkf = (float*)&g_pk;
    // float-offset map: w1 @0, w2 @432, wy @1584, wdp @2736, wdp8 @2992,
    //                   wds @3024, wds8 @3152
    if (i < 216) {                                  // conv1: 3*9*8 pairs
        int p = i & 7, t = i >> 3;
        int k = t % 9, ci = t / 9;
        pkf[2 * i]     = c1w[(2 * p) * 27 + ci * 9 + k];
        pkf[2 * i + 1] = c1w[(2 * p + 1) * 27 + ci * 9 + k];
    } else if (i < 792) {                           // conv2: 16*9*4 pairs
        int j = i - 216;
        int p = j & 3, t = j >> 2;
        int k = t % 9, ci = t / 9;
        pkf[432 + 2 * j]     = c2w[(2 * p) * 144 + ci * 9 + k];
        pkf[432 + 2 * j + 1] = c2w[(2 * p + 1) * 144 + ci * 9 + k];
    } else if (i < 1368) {                          // dconv1: 8*9*8 pairs
        int j = i - 792;
        int p = j & 7, t = j >> 3;
        int k = t % 9, ci = t / 9;
        pkf[1584 + 2 * j]     = d1w[(2 * p) * 72 + ci * 9 + k];
        pkf[1584 + 2 * j + 1] = d1w[(2 * p + 1) * 72 + ci * 9 + k];
    } else if (i < 1512) {                          // dconv2 pair (co0,co1)
        int j = i - 1368;
        int k = j % 9, ci = j / 9;
        int off = (k < 8) ? (2736 + ci * 16 + (k >> 1) * 4 + (k & 1) * 2)
                          : (2992 + ci * 2);
        pkf[off]     = d2w[ci * 9 + k];
        pkf[off + 1] = d2w[144 + ci * 9 + k];
    } else if (i < 1656) {                          // dconv2 scalar co2
        int j = i - 1512;
        int k = j % 9, ci = j / 9;
        int off = (k < 8) ? (3024 + ci * 8 + (k >> 2) * 4 + (k & 3))
                          : (3152 + ci);
        pkf[off] = d2w[288 + ci * 9 + k];
    }
}

// ---------------------------------------------------------------------------
// Fused conv1+conv2+fc: 16-row chunks, 512 threads; vector weight loads.
// ---------------------------------------------------------------------------
__global__ __launch_bounds__(512) void conv12_kernel(
    const float* __restrict__ in, const float* __restrict__ b1,
    const float* __restrict__ b2, const float* __restrict__ fcw,
    float* __restrict__ part)
{
    __shared__ float s_x[3 * 20 * 34];
    __shared__ float s_h1[16 * 18 * 34];
    __shared__ float s_b1[16];
    __shared__ float s_b2[8];
    __shared__ float swp[16][4];

    const int b  = blockIdx.y;
    const int ck = blockIdx.x;
    const int y0 = ck * 16;
    const int tid = threadIdx.x;

    if (tid < 16) s_b1[tid] = b1[tid];
    else if (tid < 24) s_b2[tid - 16] = b2[tid - 16];

    const float* inb = in + (size_t)b * 3 * 1024;
    for (int i = tid; i < 3 * 680; i += 512) {
        int c = i / 680, rem = i - c * 680;
        int r = rem / 34, xc = rem - r * 34;
        int gy = y0 - 2 + r, gx = xc - 1;
        float v = 0.f;
        if ((unsigned)gy < 32u && (unsigned)gx < 32u) v = inb[c * 1024 + gy * 32 + gx];
        s_x[i] = v;
    }
    if (tid < 36) {
        int hr = tid >> 1, xc = (tid & 1) ? 33 : 0;
#pragma unroll
        for (int c = 0; c < 16; c++) s_h1[c * 612 + hr * 34 + xc] = 0.f;
    }
    __syncthreads();

    // ---- conv1: 18 rows x 32 cols ----
    for (int it = tid; it < 576; it += 512) {
        const int hr = it >> 5, col = it & 31;
        const int gy = y0 - 1 + hr;
        if ((unsigned)gy < 32u) {
            ull acc[8];
#pragma unroll
            for (int p = 0; p < 8; p++) acc[p] = pk2(s_b1[2 * p], s_b1[2 * p + 1]);
#pragma unroll
            for (int ci = 0; ci < 3; ci++) {
                float v[9];
#pragma unroll
                for (int dy = 0; dy < 3; dy++)
#pragma unroll
                    for (int dx = 0; dx < 3; dx++)
                        v[dy * 3 + dx] = s_x[ci * 680 + (hr + dy) * 34 + col + dx];
#pragma unroll
                for (int k = 0; k < 9; k++) {
                    ull vv = pk2(v[k], v[k]);
#pragma unroll
                    for (int pp = 0; pp < 4; pp++) {
                        ulonglong2 W = c_w.w1[(ci * 9 + k) * 4 + pp];
                        acc[2 * pp]     = fma2(vv, W.x, acc[2 * pp]);
                        acc[2 * pp + 1] = fma2(vv, W.y, acc[2 * pp + 1]);
                    }
                }
            }
#pragma unroll
            for (int p = 0; p < 8; p++) {
                float lo, hi;
                upk2(acc[p], lo, hi);
                s_h1[(2 * p) * 612 + hr * 34 + col + 1]     = fmaxf(lo, 0.f);
                s_h1[(2 * p + 1) * 612 + hr * 34 + col + 1] = fmaxf(hi, 0.f);
            }
        } else {
#pragma unroll
            for (int c = 0; c < 16; c++)
                s_h1[c * 612 + hr * 34 + col + 1] = 0.f;
        }
    }
    __syncthreads();

    // ---- conv2: 512 threads = 16 rows x 32 cols + fc partials ----
    {
        const int tx = tid & 31, ty = tid >> 5;
        ull acc2[4];
#pragma unroll
        for (int p = 0; p < 4; p++) acc2[p] = pk2(s_b2[2 * p], s_b2[2 * p + 1]);
#pragma unroll
        for (int ci = 0; ci < 16; ci++) {
            float v[9];
#pragma unroll
            for (int dy = 0; dy < 3; dy++)
#pragma unroll
                for (int dx = 0; dx < 3; dx++)
                    v[dy * 3 + dx] = s_h1[ci * 612 + (ty + dy) * 34 + tx + dx];
#pragma unroll
            for (int k = 0; k < 9; k++) {
                ull vv = pk2(v[k], v[k]);
#pragma unroll
                for (int pp = 0; pp < 2; pp++) {
                    ulonglong2 W = c_w.w2[(ci * 9 + k) * 2 + pp];
                    acc2[2 * pp]     = fma2(vv, W.x, acc2[2 * pp]);
                    acc2[2 * pp + 1] = fma2(vv, W.y, acc2[2 * pp + 1]);
                }
            }
        }
        const int y = y0 + ty;
        float h[8];
#pragma unroll
        for (int p = 0; p < 4; p++) {
            float lo, hi;
            upk2(acc2[p], lo, hi);
            h[2 * p]     = fmaxf(lo, 0.f);
            h[2 * p + 1] = fmaxf(hi, 0.f);
        }
        float pr[4] = {0.f, 0.f, 0.f, 0.f};
#pragma unroll
        for (int c = 0; c < 8; c++) {
            int k = c * 1024 + y * 32 + tx;
#pragma unroll
            for (int j = 0; j < 4; j++)
                pr[j] = fmaf(h[c], __ldg(fcw + j * 8192 + k), pr[j]);
        }
#pragma unroll
        for (int off = 16; off > 0; off >>= 1)
#pragma unroll
            for (int j = 0; j < 4; j++)
                pr[j] += __shfl_down_sync(0xffffffffu, pr[j], off);
        if (tx == 0)
#pragma unroll
            for (int j = 0; j < 4; j++) swp[ty][j] = pr[j];
    }
    __syncthreads();
    if (tid < 4) {
        float s = 0.f;
#pragma unroll
        for (int wq = 0; wq < 16; wq++) s += swp[wq][tid];
        part[b * 8 + ck * 4 + tid] = s;
    }
}

// ---------------------------------------------------------------------------
// Y build: one thread per (img, pixel, channel-pair-pair half handled via pp).
// Each thread still produces one co-pair; vector load gives the pair's ull.
// ---------------------------------------------------------------------------
__global__ __launch_bounds__(256) void ybuild_kernel(
    const float* __restrict__ f2w, const float* __restrict__ f2b,
    const float* __restrict__ d1b, float* __restrict__ Y)
{
    const int idx  = blockIdx.x * 256 + threadIdx.x;
    const int px   = idx & 1023;
    const int pair = (idx >> 10) & 7;
    const int img  = idx >> 13;
    const int y = px >> 5, x = px & 31;
    const int pp = pair >> 1, half = pair & 1;

    ull acc = (img == 4) ? pk2(d1b[2 * pair], d1b[2 * pair + 1]) : pk2(0.f, 0.f);
#pragma unroll
    for (int ci = 0; ci < 8; ci++) {
#pragma unroll
        for (int dy = 0; dy < 3; dy++) {
            int gy = y + dy - 1;
            if ((unsigned)gy >= 32u) continue;
#pragma unroll
            for (int dx = 0; dx < 3; dx++) {
                int gx = x + dx - 1;
                if ((unsigned)gx >= 32u) continue;
                int k = ci * 1024 + gy * 32 + gx;
                float v = (img < 4) ? __ldg(f2w + (size_t)k * 4 + img) : __ldg(f2b + k);
                ulonglong2 W = c_w.wy[(ci * 9 + dy * 3 + dx) * 4 + pp];
                acc = fma2(pk2(v, v), half ? W.y : W.x, acc);
            }
        }
    }
    float lo, hi;
    upk2(acc, lo, hi);
    Y[img * 16384 + (2 * pair) * 1024 + px]     = lo;
    Y[img * 16384 + (2 * pair + 1) * 1024 + px] = hi;
}

// ---------------------------------------------------------------------------
// Quantum: 4 threads per batch element; each owns 4 of 16 output rows.
// ---------------------------------------------------------------------------
__global__ __launch_bounds__(128) void quantum_kernel(
    const float* __restrict__ part, const float* __restrict__ fcb,
    const float2* __restrict__ V, float* __restrict__ qout)
{
    __shared__ float2 sV[256];
    for (int i = threadIdx.x; i < 256; i += 128) sV[i] = V[i];
    __syncthreads();

    const int t = blockIdx.x * 128 + threadIdx.x;
    const int b = t >> 2, sub = t & 3;
    const int i0 = sub * 4;

    float c[4], s[4];
#pragma unroll
    for (int w = 0; w < 4; w++) {
        float ang = part[b * 8 + w] + part[b * 8 + 4 + w] + fcb[w];
        float half = ang * 0.5f;
        c[w] = cosf(half);
        s[w] = sinf(half);
    }

    float2 amp[16];
#pragma unroll
    for (int i = 0; i < 16; i++) {
        float m = ((i >> 3) & 1 ? s[0] : c[0]) * ((i >> 2) & 1 ? s[1] : c[1])
                * ((i >> 1) & 1 ? s[2] : c[2]) * ((i) & 1 ? s[3] : c[3]);
        int pc = __popc(i) & 3;
        amp[i] = (pc == 0) ? make_float2(m, 0.f)
               : (pc == 1) ? make_float2(0.f, -m)
               : (pc == 2) ? make_float2(-m, 0.f)
                           : make_float2(0.f, m);
    }

    float2 tr[4];
#pragma unroll
    for (int r = 0; r < 4; r++) tr[r] = make_float2(0.f, 0.f);
#pragma unroll
    for (int k = 0; k < 16; k++) {
        float2 a = amp[k];
#pragma unroll
        for (int r = 0; r < 4; r++) {
            float2 v = sV[(i0 + r) * 16 + k];
            tr[r].x = fmaf(v.x, a.x, fmaf(-v.y, a.y, tr[r].x));
            tr[r].y = fmaf(v.x, a.y, fmaf(v.y, a.x, tr[r].y));
        }
    }

    float ev[4] = {0.f, 0.f, 0.f, 0.f};
#pragma unroll
    for (int r = 0; r < 4; r++) {
        const int i = i0 + r;
        float p = tr[r].x * tr[r].x + tr[r].y * tr[r].y;
#pragma unroll
        for (int w = 0; w < 4; w++)
            ev[w] += (i & (1 << (3 - w))) ? -p : p;
    }
#pragma unroll
    for (int w = 0; w < 4; w++) {
        ev[w] += __shfl_xor_sync(0xffffffffu, ev[w], 1);
        ev[w] += __shfl_xor_sync(0xffffffffu, ev[w], 2);
    }
    if (sub == 0)
#pragma unroll
        for (int w = 0; w < 4; w++) qout[b * 4 + w] = ev[w];
}

// ---------------------------------------------------------------------------
// Fused output (R7 structure) with vector dconv2 weight loads.
// ---------------------------------------------------------------------------
#define YTILE 5440
__global__ __launch_bounds__(512) void fused_out_kernel(
    const float* __restrict__ q, const float* __restrict__ Y,
    const float* __restrict__ bias, float* __restrict__ out)
{
    extern __shared__ float smem[];
    float* sY = smem;
    float* sH = smem + 5 * YTILE;

    const int ck = blockIdx.x;
    const int y0 = ck * 8;
    const int b0 = blockIdx.y * 16;
    const int tid  = threadIdx.x;
    const int half = tid >> 8;
    const int htid = tid & 255;

    __shared__ float s_b[3];
    if (tid < 3) s_b[tid] = bias[tid];

    if (tid < 340) {
        const int r = tid / 34, xc = tid - 34 * r;
        const int gy = y0 + r - 1, gx = xc - 1;
        const bool ok = ((unsigned)gy < 32u) && ((unsigned)gx < 32u);
        const int goff = gy * 32 + gx;
#pragma unroll 4
        for (int pl = 0; pl < 80; pl++)
            sY[pl * 340 + tid] = ok ? __ldg(Y + pl * 1024 + goff) : 0.f;
    }
    __syncthreads();

    const int tx = htid & 31, ty = htid >> 5;
    float* sHh = sH + half * YTILE;
    const ull* sY2 = (const ull*)sY;
    ull* sH2 = (ull*)sHh;

    for (int g = 0; g < 8; g++) {
        const int b = b0 + 2 * g + half;
        const float q0 = __ldg(q + b * 4 + 0), q1 = __ldg(q + b * 4 + 1);
        const float q2 = __ldg(q + b * 4 + 2), q3 = __ldg(q + b * 4 + 3);
        const ull Q0 = pk2(q0, q0), Q1 = pk2(q1, q1);
        const ull Q2 = pk2(q2, q2), Q3 = pk2(q3, q3);

        for (int i = htid; i < 2720; i += 256) {
            ull v = fma2(Q0, sY2[i],
                    fma2(Q1, sY2[2720 + i],
                    fma2(Q2, sY2[5440 + i],
                    fma2(Q3, sY2[8160 + i], sY2[10880 + i]))));
            float lo, hi;
            upk2(v, lo, hi);
            sH2[i] = pk2(fmaxf(lo, 0.f), fmaxf(hi, 0.f));
        }
        __syncthreads();

        ull acc2 = pk2(s_b[0], s_b[1]);
        float acc = s_b[2];
#pragma unroll
        for (int ci = 0; ci < 16; ci++) {
            float v[9];
#pragma unroll
            for (int dy = 0; dy < 3; dy++)
#pragma unroll
                for (int dx = 0; dx < 3; dx++)
                    v[dy * 3 + dx] = sHh[ci * 340 + (ty + dy) * 34 + tx + dx];
            ulonglong2 wv0 = c_w.wdp[ci * 4 + 0];
            ulonglong2 wv1 = c_w.wdp[ci * 4 + 1];
            ulonglong2 wv2 = c_w.wdp[ci * 4 + 2];
            ulonglong2 wv3 = c_w.wdp[ci * 4 + 3];
            ull        w8  = c_w.wdp8[ci];
            float4 wsA = c_w.wds[ci * 2], wsB = c_w.wds[ci * 2 + 1];
            float  ws8 = c_w.wds8[ci];

            acc2 = fma2(pk2(v[0], v[0]), wv0.x, acc2);
            acc2 = fma2(pk2(v[1], v[1]), wv0.y, acc2);
            acc2 = fma2(pk2(v[2], v[2]), wv1.x, acc2);
            acc2 = fma2(pk2(v[3], v[3]), wv1.y, acc2);
            acc2 = fma2(pk2(v[4], v[4]), wv2.x, acc2);
            acc2 = fma2(pk2(v[5], v[5]), wv2.y, acc2);
            acc2 = fma2(pk2(v[6], v[6]), wv3.x, acc2);
            acc2 = fma2(pk2(v[7], v[7]), wv3.y, acc2);
            acc2 = fma2(pk2(v[8], v[8]), w8, acc2);

            acc = fmaf(v[0], wsA.x, acc);
            acc = fmaf(v[1], wsA.y, acc);
            acc = fmaf(v[2], wsA.z, acc);
            acc = fmaf(v[3], wsA.w, acc);
            acc = fmaf(v[4], wsB.x, acc);
            acc = fmaf(v[5], wsB.y, acc);
            acc = fmaf(v[6], wsB.z, acc);
            acc = fmaf(v[7], wsB.w, acc);
            acc = fmaf(v[8], ws8, acc);
        }
        float r0, r1;
        upk2(acc2, r0, r1);
        float* outp = out + (size_t)b * 3 * 1024 + (y0 + ty) * 32 + tx;
        outp[0]    = __fdividef(1.f, 1.f + __expf(-r0));
        outp[1024] = __fdividef(1.f, 1.f + __expf(-r1));
        outp[2048] = __fdividef(1.f, 1.f + __expf(-acc));
        __syncthreads();
    }
}

// ---------------------------------------------------------------------------

extern "C" void kernel_launch(void* const* d_in, const int* in_sizes, int n_in,
                              void* d_out, int out_size)
{
    const float* x   = (const float*)d_in[0];
    const float* c1w = (const float*)d_in[1];
    const float* c1b = (const float*)d_in[2];
    const float* c2w = (const float*)d_in[3];
    const float* c2b = (const float*)d_in[4];
    const float* fcw = (const float*)d_in[5];
    const float* fcb = (const float*)d_in[6];
    const float* qw  = (const float*)d_in[7];
    const float* f2w = (const float*)d_in[8];
    const float* f2b = (const float*)d_in[9];
    const float* d1w = (const float*)d_in[10];
    const float* d1b = (const float*)d_in[11];
    const float* d2w = (const float*)d_in[12];
    const float* d2b = (const float*)d_in[13];
    float* out = (float*)d_out;

    float *part, *qv, *Y, *pk;
    float2* V;
    cudaGetSymbolAddress((void**)&part, g_part);
    cudaGetSymbolAddress((void**)&qv,   g_q);
    cudaGetSymbolAddress((void**)&Y,    g_Y);
    cudaGetSymbolAddress((void**)&V,    g_V);
    cudaGetSymbolAddress((void**)&pk,   g_pk);

    cudaFuncSetAttribute(fused_out_kernel,
                         cudaFuncAttributeMaxDynamicSharedMemorySize,
                         7 * YTILE * 4);

    setup_kernel<<<8, 256>>>(c1w, c2w, d1w, d2w, qw, V);
    cudaMemcpyToSymbolAsync(c_w, pk, sizeof(CW), 0, cudaMemcpyDeviceToDevice, 0);

    ybuild_kernel<<<160, 256>>>(f2w, f2b, d1b, Y);
    conv12_kernel<<<dim3(2, BATCH), 512>>>(x, c1b, c2b, fcw, part);
    quantum_kernel<<<BATCH / 32, 128>>>(part, fcb, V, qv);
    fused_out_kernel<<<dim3(4, BATCH / 16), 512, 7 * YTILE * 4>>>(qv, Y, d2b, out);
}